// round 4
// baseline (speedup 1.0000x reference)
#include <cuda_runtime.h>
#include <cstdint>

// one_hot: label (4096x4096 int32) -> out (8, 4096, 4096) float32
// out[n, h, w] = (label[h, w] == n) ? 1.0f : 0.0f
//
// Pure HBM streaming: 64 MiB read + 512 MiB write (~75.5us floor at 8 TB/s).
// R1 (1 vec/thread, coalesced): 94us, DRAM=70.8%.
// R2 (2 adjacent vecs/thread): BROKE per-instruction coalescing (32B lane
//     stride), L1=80.7%, 144us.
// R3: 2 vecs/thread at +BLK offset -> every LDG/STG has contiguous 16B lanes,
//     while keeping 2x in-flight loads + 16 store streams per thread.

#define H 4096
#define W 4096
#define NCLS 8
#define HW (H * W)             // 16777216
#define NVEC (HW / 4)          // 4194304 float4/int4 vectors per plane
#define BLK 256
#define VPT 2
#define VPB (BLK * VPT)        // 512 vectors per block
#define NBLOCKS (NVEC / VPB)   // 8192

__global__ void __launch_bounds__(BLK) onehot_kernel(
    const int4* __restrict__ lab4, float4* __restrict__ out4)
{
    unsigned i = blockIdx.x * (unsigned)VPB + threadIdx.x;  // first vector
    int4 a = __ldcs(lab4 + i);
    int4 b = __ldcs(lab4 + i + BLK);   // second vector, still lane-contiguous

#pragma unroll
    for (int n = 0; n < NCLS; n++) {
        float4 va, vb;
        va.x = (a.x == n) ? 1.0f : 0.0f;
        va.y = (a.y == n) ? 1.0f : 0.0f;
        va.z = (a.z == n) ? 1.0f : 0.0f;
        va.w = (a.w == n) ? 1.0f : 0.0f;
        vb.x = (b.x == n) ? 1.0f : 0.0f;
        vb.y = (b.y == n) ? 1.0f : 0.0f;
        vb.z = (b.z == n) ? 1.0f : 0.0f;
        vb.w = (b.w == n) ? 1.0f : 0.0f;
        size_t base = (size_t)n * NVEC + i;
        __stcs(out4 + base, va);
        __stcs(out4 + base + BLK, vb);
    }
}

extern "C" void kernel_launch(void* const* d_in, const int* in_sizes, int n_in,
                              void* d_out, int out_size)
{
    const int4* lab4 = (const int4*)d_in[0];
    float4* out4 = (float4*)d_out;
    onehot_kernel<<<NBLOCKS, BLK>>>(lab4, out4);
}

// round 5
// speedup vs baseline: 1.0420x; 1.0420x over previous
#include <cuda_runtime.h>
#include <cstdint>

// one_hot: label (4096x4096 int32) -> out (8, 4096, 4096) float32
// out[n, h, w] = (label[h, w] == n) ? 1.0f : 0.0f
//
// Pure HBM streaming: 64 MiB read + 512 MiB write (~75.5us floor at 8 TB/s).
// R1 (1 int4/thread):        94us, DRAM=70.8%
// R2 (adjacent 2/thread):   144us  (broke per-instruction coalescing)
// R3 (strided 2/thread):     97us, DRAM=68.8%  (queue depth: no effect)
// R4: 256-bit stores (sm_100a st.global.v8.f32). 8 labels/thread, one 32B
//     store per plane -> 2x bytes/instruction, minimal issue overhead.

#define H 4096
#define W 4096
#define NCLS 8
#define HW (H * W)             // 16777216
#define LPT 8                  // labels (and floats per plane) per thread
#define BLK 256
#define NTHREADS (HW / LPT)    // 2097152
#define NBLOCKS (NTHREADS / BLK)   // 8192

__device__ __forceinline__ void st256_cs(float* p, const float* v)
{
    asm volatile(
        "st.global.cs.v8.f32 [%0], {%1,%2,%3,%4,%5,%6,%7,%8};"
        :: "l"(p),
           "f"(v[0]), "f"(v[1]), "f"(v[2]), "f"(v[3]),
           "f"(v[4]), "f"(v[5]), "f"(v[6]), "f"(v[7])
        : "memory");
}

__global__ void __launch_bounds__(BLK) onehot_kernel(
    const int4* __restrict__ lab4, float* __restrict__ out)
{
    // thread handles 8 consecutive labels: elements [8*g, 8*g+8)
    unsigned g = blockIdx.x * (unsigned)BLK + threadIdx.x;
    const int4* p = lab4 + (size_t)g * 2;
    int4 a = __ldcs(p);
    int4 b = __ldcs(p + 1);
    int l[8] = { a.x, a.y, a.z, a.w, b.x, b.y, b.z, b.w };

    size_t base = (size_t)g * LPT;
#pragma unroll
    for (int n = 0; n < NCLS; n++) {
        float v[8];
#pragma unroll
        for (int k = 0; k < 8; k++)
            v[k] = (l[k] == n) ? 1.0f : 0.0f;
        st256_cs(out + (size_t)n * HW + base, v);
    }
}

extern "C" void kernel_launch(void* const* d_in, const int* in_sizes, int n_in,
                              void* d_out, int out_size)
{
    const int4* lab4 = (const int4*)d_in[0];
    float* out = (float*)d_out;
    onehot_kernel<<<NBLOCKS, BLK>>>(lab4, out);
}

// round 6
// speedup vs baseline: 1.0547x; 1.0122x over previous
#include <cuda_runtime.h>
#include <cstdint>

// one_hot: label (4096x4096 int32) -> out (8, 4096, 4096) float32
// out[n, h, w] = (label[h, w] == n) ? 1.0f : 0.0f
//
// Pure HBM streaming: 64 MiB read + 512 MiB write (~75.5us floor at 8 TB/s).
// R1 (1 int4/thread, .cs):     94.3us, DRAM=70.8%
// R2 (adjacent 2/thread):     144us   (broke per-instruction coalescing)
// R3 (strided 2/thread):       97.2us (queue depth: no effect)
// R4 (v8.f32 .cs stores):      93.8us, DRAM=71.3% (issue density: no effect)
// R5: SAME as R4 but default write-back stores (no .cs). Hypothesis: evict-
//     first drains L2 eagerly/fragmented; write-back lets the DRAM scheduler
//     batch rows. Single-variable change.

#define H 4096
#define W 4096
#define NCLS 8
#define HW (H * W)             // 16777216
#define LPT 8                  // labels (and floats per plane) per thread
#define BLK 256
#define NTHREADS (HW / LPT)    // 2097152
#define NBLOCKS (NTHREADS / BLK)   // 8192

__device__ __forceinline__ void st256(float* p, const float* v)
{
    asm volatile(
        "st.global.v8.f32 [%0], {%1,%2,%3,%4,%5,%6,%7,%8};"
        :: "l"(p),
           "f"(v[0]), "f"(v[1]), "f"(v[2]), "f"(v[3]),
           "f"(v[4]), "f"(v[5]), "f"(v[6]), "f"(v[7])
        : "memory");
}

__global__ void __launch_bounds__(BLK) onehot_kernel(
    const int4* __restrict__ lab4, float* __restrict__ out)
{
    // thread handles 8 consecutive labels: elements [8*g, 8*g+8)
    unsigned g = blockIdx.x * (unsigned)BLK + threadIdx.x;
    const int4* p = lab4 + (size_t)g * 2;
    int4 a = __ldcs(p);
    int4 b = __ldcs(p + 1);
    int l[8] = { a.x, a.y, a.z, a.w, b.x, b.y, b.z, b.w };

    size_t base = (size_t)g * LPT;
#pragma unroll
    for (int n = 0; n < NCLS; n++) {
        float v[8];
#pragma unroll
        for (int k = 0; k < 8; k++)
            v[k] = (l[k] == n) ? 1.0f : 0.0f;
        st256(out + (size_t)n * HW + base, v);
    }
}

extern "C" void kernel_launch(void* const* d_in, const int* in_sizes, int n_in,
                              void* d_out, int out_size)
{
    const int4* lab4 = (const int4*)d_in[0];
    float* out = (float*)d_out;
    onehot_kernel<<<NBLOCKS, BLK>>>(lab4, out);
}